// round 9
// baseline (speedup 1.0000x reference)
#include <cuda_runtime.h>
#include <cuda_bf16.h>
#include <cstdint>
#include <math.h>

#define NN 50000
#define NE 800000
#define NF 256
#define NH 128
#define NC 40
#define NCP 64   // padded row stride for g_g2 (256B-aligned rows)

// ---- scratch (static device globals; module-load allocation, legal) ----
__device__ int   g_deg[NN];
__device__ int   g_cur[NN];
__device__ int   g_offs[NN + 1];
__device__ int   g_csr[NE];
__device__ float g_dinv[NN];
__device__ float g_g1[(size_t)NN * NH];    // dinv[i] * (x @ W1)[i]
__device__ float g_a1[(size_t)NN * NH];    // relu(aggregated layer1 + b1)
__device__ float g_g2[(size_t)NN * NCP];   // dinv[i] * (a1 @ W2)[i], padded rows

// ---------------------------------------------------------------
__global__ void k_zero() {
    int i = blockIdx.x * blockDim.x + threadIdx.x;
    if (i < NN) { g_deg[i] = 0; g_cur[i] = 0; }
}

__global__ void k_hist(const int* __restrict__ dst) {
    int i = blockIdx.x * blockDim.x + threadIdx.x;
    if (i < NE) atomicAdd(&g_deg[dst[i]], 1);
}

// exclusive prefix sum over g_deg (1 block), also computes dinv = rsqrt(indeg+1)
__global__ void k_scan() {
    __shared__ int sh[1024];
    __shared__ int carry;
    int tid = threadIdx.x;
    if (tid == 0) { carry = 0; g_offs[0] = 0; }
    __syncthreads();
    for (int base = 0; base < NN; base += 1024) {
        int i = base + tid;
        int v = (i < NN) ? g_deg[i] : 0;
        if (i < NN) g_dinv[i] = rsqrtf((float)(v + 1));  // +1 = self loop
        sh[tid] = v;
        __syncthreads();
        for (int off = 1; off < 1024; off <<= 1) {
            int t = 0;
            if (tid >= off) t = sh[tid - off];
            __syncthreads();
            if (tid >= off) sh[tid] += t;
            __syncthreads();
        }
        if (i < NN) g_offs[i + 1] = carry + sh[tid];
        __syncthreads();
        if (tid == 0) carry += sh[1023];
        __syncthreads();
    }
}

__global__ void k_scatter(const int* __restrict__ src, const int* __restrict__ dst) {
    int i = blockIdx.x * blockDim.x + threadIdx.x;
    if (i < NE) {
        int d = dst[i];
        int pos = g_offs[d] + atomicAdd(&g_cur[d], 1);
        g_csr[pos] = src[i];
    }
}

// ---------------------------------------------------------------
// GEMM1 (tensor core): g1 = dinv[row] * (X[NN,256] @ W1[256,128])
// bf16 2-way split (hi+lo), 3 products: hi*Hi + hi*Lo + lo*Hi. Error ~2^-16.
// BM=128, BN=128, BK=32; 8 warps: wm = wid/4 (m64), wn = wid%4 (n32).
// mma.sync.m16n8k16; fragments loaded as plain 32-bit LDS (bank-perfect pad 40).

#define APAD 40   // row stride (bf16 elems): row*20 words mod 32 covers all banks

__device__ __forceinline__ void bf_split(float v, __nv_bfloat16& h, __nv_bfloat16& l) {
    h = __float2bfloat16(v);
    l = __float2bfloat16(v - __bfloat162float(h));
}

#define MMA_BF16(d, a, b)                                                     \
    asm volatile(                                                             \
        "mma.sync.aligned.m16n8k16.row.col.f32.bf16.bf16.f32 "                \
        "{%0,%1,%2,%3},{%4,%5,%6,%7},{%8,%9},{%0,%1,%2,%3};"                  \
        : "+f"(d[0]), "+f"(d[1]), "+f"(d[2]), "+f"(d[3])                      \
        : "r"(a[0]), "r"(a[1]), "r"(a[2]), "r"(a[3]), "r"(b[0]), "r"(b[1]))

__global__ void __launch_bounds__(256) k_gemm1(const float* __restrict__ X,
                                               const float* __restrict__ W) {
    __shared__ __nv_bfloat16 As_hi[128][APAD];
    __shared__ __nv_bfloat16 As_lo[128][APAD];
    __shared__ __nv_bfloat16 Bs_hi[128][APAD];   // [n][k]
    __shared__ __nv_bfloat16 Bs_lo[128][APAD];

    int tid  = threadIdx.x;
    int wid  = tid >> 5;
    int lane = tid & 31;
    int wm   = wid >> 2;          // 0..1  -> m offset wm*64
    int wn   = wid & 3;           // 0..3  -> n offset wn*32
    int rowbase = blockIdx.x * 128;
    int rA = lane >> 2;           // 0..7 row-in-group
    int kq = (lane & 3) * 2;      // k pair base

    float acc[4][4][4];
#pragma unroll
    for (int f = 0; f < 4; f++)
#pragma unroll
        for (int g = 0; g < 4; g++)
#pragma unroll
            for (int c = 0; c < 4; c++) acc[f][g][c] = 0.f;

    for (int kt = 0; kt < NF; kt += 32) {
        // --- A tile: 128x32 f32 -> bf16 hi/lo ---
#pragma unroll
        for (int l = 0; l < 4; l++) {
            int idx = tid + l * 256;          // 0..1023
            int r = idx >> 3, q = idx & 7;    // 8 float4 per row
            int grow = rowbase + r;
            float4 v = make_float4(0.f, 0.f, 0.f, 0.f);
            if (grow < NN) v = *(const float4*)&X[(size_t)grow * NF + kt + q * 4];
            __nv_bfloat16 hx, lx, hy, ly, hz, lz, hw, lw;
            bf_split(v.x, hx, lx); bf_split(v.y, hy, ly);
            bf_split(v.z, hz, lz); bf_split(v.w, hw, lw);
            *(__nv_bfloat162*)&As_hi[r][q * 4]     = __nv_bfloat162(hx, hy);
            *(__nv_bfloat162*)&As_hi[r][q * 4 + 2] = __nv_bfloat162(hz, hw);
            *(__nv_bfloat162*)&As_lo[r][q * 4]     = __nv_bfloat162(lx, ly);
            *(__nv_bfloat162*)&As_lo[r][q * 4 + 2] = __nv_bfloat162(lz, lw);
        }
        // --- B tile: W[kt..kt+31][0..127] f32 -> transposed bf16 hi/lo [n][k] ---
#pragma unroll
        for (int l = 0; l < 4; l++) {
            int idx = tid + l * 256;
            int k = idx >> 5, n4 = idx & 31;  // 32 float4 per k-row
            float4 v = *(const float4*)&W[(size_t)(kt + k) * NH + n4 * 4];
            __nv_bfloat16 h, lo;
            bf_split(v.x, h, lo); Bs_hi[n4 * 4 + 0][k] = h; Bs_lo[n4 * 4 + 0][k] = lo;
            bf_split(v.y, h, lo); Bs_hi[n4 * 4 + 1][k] = h; Bs_lo[n4 * 4 + 1][k] = lo;
            bf_split(v.z, h, lo); Bs_hi[n4 * 4 + 2][k] = h; Bs_lo[n4 * 4 + 2][k] = lo;
            bf_split(v.w, h, lo); Bs_hi[n4 * 4 + 3][k] = h; Bs_lo[n4 * 4 + 3][k] = lo;
        }
        __syncthreads();

#pragma unroll
        for (int ks = 0; ks < 2; ks++) {
            int kb = ks * 16 + kq;
            uint32_t Bh[4][2], Bl[4][2];
#pragma unroll
            for (int g = 0; g < 4; g++) {
                int col = wn * 32 + g * 8 + rA;
                Bh[g][0] = *(const uint32_t*)&Bs_hi[col][kb];
                Bh[g][1] = *(const uint32_t*)&Bs_hi[col][kb + 8];
                Bl[g][0] = *(const uint32_t*)&Bs_lo[col][kb];
                Bl[g][1] = *(const uint32_t*)&Bs_lo[col][kb + 8];
            }
#pragma unroll
            for (int f = 0; f < 4; f++) {
                int row = wm * 64 + f * 16 + rA;
                uint32_t Ah[4], Al[4];
                Ah[0] = *(const uint32_t*)&As_hi[row][kb];
                Ah[1] = *(const uint32_t*)&As_hi[row + 8][kb];
                Ah[2] = *(const uint32_t*)&As_hi[row][kb + 8];
                Ah[3] = *(const uint32_t*)&As_hi[row + 8][kb + 8];
                Al[0] = *(const uint32_t*)&As_lo[row][kb];
                Al[1] = *(const uint32_t*)&As_lo[row + 8][kb];
                Al[2] = *(const uint32_t*)&As_lo[row][kb + 8];
                Al[3] = *(const uint32_t*)&As_lo[row + 8][kb + 8];
#pragma unroll
                for (int g = 0; g < 4; g++) {
                    MMA_BF16(acc[f][g], Ah, Bh[g]);
                    MMA_BF16(acc[f][g], Ah, Bl[g]);
                    MMA_BF16(acc[f][g], Al, Bh[g]);
                }
            }
        }
        __syncthreads();
    }

    // epilogue: scale by dinv, store
#pragma unroll
    for (int f = 0; f < 4; f++) {
        int r0 = rowbase + wm * 64 + f * 16 + rA;
#pragma unroll
        for (int h = 0; h < 2; h++) {
            int row = r0 + h * 8;
            if (row < NN) {
                float di = g_dinv[row];
#pragma unroll
                for (int g = 0; g < 4; g++) {
                    float2 o;
                    o.x = acc[f][g][h * 2 + 0] * di;
                    o.y = acc[f][g][h * 2 + 1] * di;
                    *(float2*)&g_g1[(size_t)row * NH + wn * 32 + g * 8 + kq] = o;
                }
            }
        }
    }
}

// ---------------------------------------------------------------
// agg1: one warp per node.  a1 = relu(dinv[d]*(sum_{e:dst=d} g1[src] + g1[d]) + b1)
__global__ void __launch_bounds__(256) k_agg1(const float* __restrict__ b1) {
    int warp = (blockIdx.x * blockDim.x + threadIdx.x) >> 5;
    int lane = threadIdx.x & 31;
    if (warp >= NN) return;
    int node = warp;

    float4 acc = *(const float4*)&g_g1[(size_t)node * NH + lane * 4];  // self loop
    int s0 = g_offs[node], s1 = g_offs[node + 1];
    for (int base = s0; base < s1; base += 32) {
        int e = base + lane;
        int sidx = (e < s1) ? __ldg(&g_csr[e]) : 0;
        int cnt = min(32, s1 - base);
#pragma unroll 1
        for (int j = 0; j < cnt; j++) {
            int sj = __shfl_sync(0xffffffffu, sidx, j);
            float4 v = __ldg((const float4*)&g_g1[(size_t)sj * NH + lane * 4]);
            acc.x += v.x; acc.y += v.y; acc.z += v.z; acc.w += v.w;
        }
    }
    float di = g_dinv[node];
    float4 bb = *(const float4*)&b1[lane * 4];
    float4 o;
    o.x = fmaxf(di * acc.x + bb.x, 0.f);
    o.y = fmaxf(di * acc.y + bb.y, 0.f);
    o.z = fmaxf(di * acc.z + bb.z, 0.f);
    o.w = fmaxf(di * acc.w + bb.w, 0.f);
    *(float4*)&g_a1[(size_t)node * NH + lane * 4] = o;
}

// ---------------------------------------------------------------
// GEMM2: g2 = dinv[row] * (a1[NN,128] @ W2[128,40]), rows padded to NCP.
__global__ void __launch_bounds__(320) k_gemm2(const float* __restrict__ W2) {
    __shared__ float As[48][128];    // natural row-major
    __shared__ float Wt[40][132];    // transposed W2, padded
    int tid = threadIdx.x;
    int rowbase = blockIdx.x * 48;

    // load A tile: 48x128 = 1536 float4
    for (int idx = tid; idx < 1536; idx += 320) {
        int r = idx >> 5, k4 = idx & 31;
        int grow = rowbase + r;
        float4 v = make_float4(0.f, 0.f, 0.f, 0.f);
        if (grow < NN) v = *(const float4*)&g_a1[(size_t)grow * NH + k4 * 4];
        *(float4*)&As[r][k4 * 4] = v;
    }
    // load W2 transposed: 128x40 floats
    for (int idx = tid; idx < NH * NC; idx += 320) {
        int k = idx / NC, c = idx % NC;
        Wt[c][k] = W2[idx];
    }
    __syncthreads();

    int col  = tid % 40;
    int rowg = tid / 40;            // 0..7
    float acc[6];
#pragma unroll
    for (int r = 0; r < 6; r++) acc[r] = 0.f;

#pragma unroll 4
    for (int k = 0; k < NH; k += 4) {
        float4 w4 = *(float4*)&Wt[col][k];
#pragma unroll
        for (int r = 0; r < 6; r++) {
            float4 a4 = *(float4*)&As[rowg * 6 + r][k];
            acc[r] += a4.x * w4.x + a4.y * w4.y + a4.z * w4.z + a4.w * w4.w;
        }
    }
#pragma unroll
    for (int r = 0; r < 6; r++) {
        int row = rowbase + rowg * 6 + r;
        if (row < NN)
            g_g2[(size_t)row * NCP + col] = acc[r] * g_dinv[row];
    }
}

// ---------------------------------------------------------------
// agg2 + bias + log_softmax, one warp per node. 40 feats: lane and lane+32 (<8).
__global__ void __launch_bounds__(256) k_agg2(const float* __restrict__ b2,
                                              float* __restrict__ out) {
    int warp = (blockIdx.x * blockDim.x + threadIdx.x) >> 5;
    int lane = threadIdx.x & 31;
    if (warp >= NN) return;
    int node = warp;
    size_t rb = (size_t)node * NCP;

    float a0 = g_g2[rb + lane];                                  // self loop
    float a1v = (lane < 8) ? g_g2[rb + 32 + lane] : 0.f;
    int s0 = g_offs[node], s1 = g_offs[node + 1];
    for (int base = s0; base < s1; base += 32) {
        int e = base + lane;
        int sidx = (e < s1) ? __ldg(&g_csr[e]) : 0;
        int cnt = min(32, s1 - base);
#pragma unroll 1
        for (int j = 0; j < cnt; j++) {
            int sj = __shfl_sync(0xffffffffu, sidx, j);
            size_t sb = (size_t)sj * NCP;
            a0 += __ldg(&g_g2[sb + lane]);
            if (lane < 8) a1v += __ldg(&g_g2[sb + 32 + lane]);
        }
    }
    float di = g_dinv[node];
    float v0 = di * a0 + b2[lane];
    float v1 = (lane < 8) ? (di * a1v + b2[32 + lane]) : -INFINITY;

    float m = fmaxf(v0, v1);
#pragma unroll
    for (int o = 16; o > 0; o >>= 1) m = fmaxf(m, __shfl_xor_sync(0xffffffffu, m, o));
    float s = expf(v0 - m) + ((lane < 8) ? expf(v1 - m) : 0.f);
#pragma unroll
    for (int o = 16; o > 0; o >>= 1) s += __shfl_xor_sync(0xffffffffu, s, o);
    float lse = m + logf(s);

    size_t ob = (size_t)node * NC;
    out[ob + lane] = v0 - lse;
    if (lane < 8) out[ob + 32 + lane] = v1 - lse;
}

// ---------------------------------------------------------------
extern "C" void kernel_launch(void* const* d_in, const int* in_sizes, int n_in,
                              void* d_out, int out_size) {
    const float* x  = (const float*)d_in[0];
    const int*   ei = (const int*)d_in[1];
    const float* W1 = (const float*)d_in[2];
    const float* b1 = (const float*)d_in[3];
    const float* W2 = (const float*)d_in[4];
    const float* b2 = (const float*)d_in[5];
    float* out = (float*)d_out;
    const int* src = ei;
    const int* dst = ei + NE;

    k_zero<<<(NN + 255) / 256, 256>>>();
    k_hist<<<(NE + 255) / 256, 256>>>(dst);
    k_scan<<<1, 1024>>>();
    k_scatter<<<(NE + 255) / 256, 256>>>(src, dst);
    k_gemm1<<<(NN + 127) / 128, 256>>>(x, W1);
    k_agg1<<<(NN + 7) / 8, 256>>>(b1);
    k_gemm2<<<(NN + 47) / 48, 320>>>(W2);
    k_agg2<<<(NN + 7) / 8, 256>>>(b2, out);
}